// round 9
// baseline (speedup 1.0000x reference)
#include <cuda_runtime.h>
#include <math.h>

#define NB 2
#define NS 2048
#define ND 1024
#define NH 16
#define NDK 64

// Scratch: projected Q/K/V [B,S,D] fp32 (head h = cols h*64..h*64+63),
// plus full score matrix in order-preserving mono-u32 [BH][S][S] (512 MB).
__device__ float g_Qp[NB * NS * ND];
__device__ float g_Kp[NB * NS * ND];
__device__ float g_Vp[NB * NS * ND];
__device__ unsigned g_S[(size_t)NB * NH * NS * NS];

// ---------------------------------------------------------------------------
// Helpers
// ---------------------------------------------------------------------------
__device__ __forceinline__ float warp_max(float v) {
#pragma unroll
    for (int off = 16; off > 0; off >>= 1)
        v = fmaxf(v, __shfl_xor_sync(0xffffffffu, v, off));
    return v;
}
__device__ __forceinline__ float warp_sum(float v) {
#pragma unroll
    for (int off = 16; off > 0; off >>= 1)
        v += __shfl_xor_sync(0xffffffffu, v, off);
    return v;
}
// Monotone float<->uint transform: u-order == float-order (finite values).
__device__ __forceinline__ unsigned f2mono(float f) {
    unsigned b = __float_as_uint(f);
    return (b & 0x80000000u) ? ~b : (b | 0x80000000u);
}
__device__ __forceinline__ float mono2f(unsigned u) {
    unsigned b = (u & 0x80000000u) ? (u ^ 0x80000000u) : ~u;
    return __uint_as_float(b);
}
// Packed dual-FMA: acc.{lo,hi} += a.{lo,hi} * b.{lo,hi}
__device__ __forceinline__ void ffma2(unsigned long long& acc,
                                      unsigned long long a,
                                      unsigned long long b) {
    asm("fma.rn.f32x2 %0, %1, %2, %0;" : "+l"(acc) : "l"(a), "l"(b));
}
union F4U2 { float4 f; unsigned long long u[2]; float s[4]; };

// ---------------------------------------------------------------------------
// Projection GEMM (FFMA2, dup-free): C = relu(A @ W + bias), M=4096, N=K=1024.
// A tile stored DUPLICATED in smem (AsD[k][2m]=AsD[k][2m+1]=a_m) so packed
// [a,a] operands come straight from broadcast LDS.128 — no MOV duplication.
// BK=16, double-buffered, one __syncthreads per k-step.
// ---------------------------------------------------------------------------
__global__ __launch_bounds__(256, 2) void proj_kernel(
    const float* __restrict__ X0, const float* __restrict__ W0, const float* __restrict__ B0,
    const float* __restrict__ X1, const float* __restrict__ W1, const float* __restrict__ B1,
    const float* __restrict__ X2, const float* __restrict__ W2, const float* __restrict__ B2)
{
    const int N = ND, K = ND;
    const int z = blockIdx.z;
    const float* A    = (z == 0) ? X0 : (z == 1) ? X1 : X2;
    const float* W    = (z == 0) ? W0 : (z == 1) ? W1 : W2;
    const float* bias = (z == 0) ? B0 : (z == 1) ? B1 : B2;
    float* C          = (z == 0) ? g_Qp : (z == 1) ? g_Kp : g_Vp;

    __shared__ float AsD[2][16][256];   // duplicated A: [buf][k][2m(+1)] (32 KB)
    __shared__ float Bs[2][16][128];    // [buf][k][n]                    (16 KB)

    const int tid = threadIdx.x;
    const int tx = tid & 15;
    const int ty = tid >> 4;
    const int brow = blockIdx.y * 128;
    const int bcol = blockIdx.x * 128;

    const int ar = tid >> 1;            // A row within tile (0..127)
    const int ak = (tid & 1) << 3;      // A k-offset (0 or 8)
    const int wr = tid >> 4;            // W k-row within slab (0..15)
    const int wc = (tid & 15) << 3;     // W col (0..120)

    unsigned long long accp[8][4];
#pragma unroll
    for (int i = 0; i < 8; i++)
#pragma unroll
        for (int q = 0; q < 4; q++) accp[i][q] = 0ull;

    const float* Aptr = A + (size_t)(brow + ar) * K + ak;
    const float* Wptr = W + (size_t)wr * N + bcol + wc;

    float4 a0 = *(const float4*)(Aptr);
    float4 a1 = *(const float4*)(Aptr + 4);
    float4 w0 = *(const float4*)(Wptr);
    float4 w1 = *(const float4*)(Wptr + 4);

    int p = 0;
    for (int k0 = 0; k0 < K; k0 += 16) {
        // commit staged tile to buffer p (A stored duplicated, STS.64)
        {
            const float av[8] = {a0.x, a0.y, a0.z, a0.w, a1.x, a1.y, a1.z, a1.w};
#pragma unroll
            for (int j = 0; j < 8; j++)
                *(float2*)&AsD[p][ak + j][2 * ar] = make_float2(av[j], av[j]);
        }
        *(float4*)&Bs[p][wr][wc] = w0;
        *(float4*)&Bs[p][wr][wc + 4] = w1;
        __syncthreads();
        // stage next tile (in flight during compute below)
        if (k0 + 16 < K) {
            a0 = *(const float4*)(Aptr + k0 + 16);
            a1 = *(const float4*)(Aptr + k0 + 20);
            w0 = *(const float4*)(Wptr + (size_t)(k0 + 16) * N);
            w1 = *(const float4*)(Wptr + (size_t)(k0 + 16) * N + 4);
        }
#pragma unroll
        for (int k = 0; k < 16; k++) {
            F4U2 A0, A1, A2, A3, b0, b1;
            A0.f = *(const float4*)&AsD[p][k][8 * ty];            // rows ty4+0,1
            A1.f = *(const float4*)&AsD[p][k][8 * ty + 4];        // rows ty4+2,3
            A2.f = *(const float4*)&AsD[p][k][128 + 8 * ty];      // rows 64+ty4+0,1
            A3.f = *(const float4*)&AsD[p][k][128 + 8 * ty + 4];  // rows 64+ty4+2,3
            b0.f = *(const float4*)&Bs[p][k][tx * 4];
            b1.f = *(const float4*)&Bs[p][k][64 + tx * 4];
            unsigned long long ap[8] = {A0.u[0], A0.u[1], A1.u[0], A1.u[1],
                                        A2.u[0], A2.u[1], A3.u[0], A3.u[1]};
            unsigned long long bp[4] = {b0.u[0], b0.u[1], b1.u[0], b1.u[1]};
#pragma unroll
            for (int i = 0; i < 8; i++)
#pragma unroll
                for (int q = 0; q < 4; q++) ffma2(accp[i][q], ap[i], bp[q]);
        }
        p ^= 1;
    }

#pragma unroll
    for (int i = 0; i < 8; i++) {
        const int r = brow + ((i < 4) ? (ty * 4 + i) : (64 + ty * 4 + (i - 4)));
        const float2* ap = (const float2*)&accp[i][0];
        {
            const int c = bcol + tx * 4;
            float4 v;
            v.x = fmaxf(ap[0].x + bias[c + 0], 0.0f);
            v.y = fmaxf(ap[0].y + bias[c + 1], 0.0f);
            v.z = fmaxf(ap[1].x + bias[c + 2], 0.0f);
            v.w = fmaxf(ap[1].y + bias[c + 3], 0.0f);
            *(float4*)(C + (size_t)r * N + c) = v;
        }
        {
            const int c = bcol + 64 + tx * 4;
            float4 v;
            v.x = fmaxf(ap[2].x + bias[c + 0], 0.0f);
            v.y = fmaxf(ap[2].y + bias[c + 1], 0.0f);
            v.z = fmaxf(ap[3].x + bias[c + 2], 0.0f);
            v.w = fmaxf(ap[3].y + bias[c + 3], 0.0f);
            *(float4*)(C + (size_t)r * N + c) = v;
        }
    }
}

// ---------------------------------------------------------------------------
// Phase A: score GEMM. Per (b,h): S = (Qh @ Kh^T) / 8, written as mono-u32.
// Q tile stored duplicated (dup-free FFMA2 operands), K tile natural.
// 128x128 tile / CTA, K=64 in two 32-wide phases. Grid = (16, 16, 32).
// Accumulation order identical to prior rounds -> bit-identical scores.
// ---------------------------------------------------------------------------
#define ADS 264   // duplicated A row stride (floats), 16B-aligned
#define BDS 132   // B row stride
#define SCORE_SMEM ((32 * ADS + 32 * BDS) * 4)

__global__ __launch_bounds__(256, 2) void score_kernel()
{
    extern __shared__ float smem_s[];
    float* AsD = smem_s;                 // [32][ADS] duplicated Q^T
    float* Bs  = smem_s + 32 * ADS;      // [32][BDS] K^T

    const int bh = blockIdx.z;
    const int b = bh >> 4, h = bh & 15;
    const int brow = blockIdx.y * 128;
    const int bcol = blockIdx.x * 128;
    const int tid = threadIdx.x;
    const int tx = tid & 15;
    const int ty = tid >> 4;

    const float* Qb = g_Qp + (size_t)b * NS * ND + h * NDK;
    const float* Kb = g_Kp + (size_t)b * NS * ND + h * NDK;

    unsigned long long accp[8][4];
#pragma unroll
    for (int i = 0; i < 8; i++)
#pragma unroll
        for (int q = 0; q < 4; q++) accp[i][q] = 0ull;

    const int d4 = tid & 7;      // float4 index within 32-wide k chunk
    const int rr = tid >> 3;     // 0..31

    for (int kc = 0; kc < 2; kc++) {
        __syncthreads();
#pragma unroll
        for (int c = 0; c < 4; c++) {
            const int r = rr + c * 32;
            float4 qa = *(const float4*)(Qb + (size_t)(brow + r) * ND + kc * 32 + d4 * 4);
            const float qv[4] = {qa.x, qa.y, qa.z, qa.w};
#pragma unroll
            for (int j = 0; j < 4; j++)
                *(float2*)&AsD[(d4 * 4 + j) * ADS + 2 * r] = make_float2(qv[j], qv[j]);
            float4 kb = *(const float4*)(Kb + (size_t)(bcol + r) * ND + kc * 32 + d4 * 4);
            Bs[(d4 * 4 + 0) * BDS + r] = kb.x;
            Bs[(d4 * 4 + 1) * BDS + r] = kb.y;
            Bs[(d4 * 4 + 2) * BDS + r] = kb.z;
            Bs[(d4 * 4 + 3) * BDS + r] = kb.w;
        }
        __syncthreads();
#pragma unroll 8
        for (int k = 0; k < 32; k++) {
            F4U2 A0, A1, A2, A3, b0, b1;
            A0.f = *(const float4*)&AsD[k * ADS + 8 * ty];
            A1.f = *(const float4*)&AsD[k * ADS + 8 * ty + 4];
            A2.f = *(const float4*)&AsD[k * ADS + 128 + 8 * ty];
            A3.f = *(const float4*)&AsD[k * ADS + 128 + 8 * ty + 4];
            b0.f = *(const float4*)&Bs[k * BDS + tx * 4];
            b1.f = *(const float4*)&Bs[k * BDS + 64 + tx * 4];
            unsigned long long ap[8] = {A0.u[0], A0.u[1], A1.u[0], A1.u[1],
                                        A2.u[0], A2.u[1], A3.u[0], A3.u[1]};
            unsigned long long bp[4] = {b0.u[0], b0.u[1], b1.u[0], b1.u[1]};
#pragma unroll
            for (int i = 0; i < 8; i++)
#pragma unroll
                for (int q = 0; q < 4; q++) ffma2(accp[i][q], ap[i], bp[q]);
        }
    }

    // epilogue: scale by 1/8, mono-transform, store u32
    unsigned* Sb = g_S + (size_t)bh * NS * NS;
#pragma unroll
    for (int i = 0; i < 8; i++) {
        const int row = brow + ((i < 4) ? (ty * 4 + i) : (64 + ty * 4 + (i - 4)));
        unsigned* srow = Sb + (size_t)row * NS;
        const float2* ap = (const float2*)&accp[i][0];
        uint4 u0, u1;
        u0.x = f2mono(ap[0].x * 0.125f);
        u0.y = f2mono(ap[0].y * 0.125f);
        u0.z = f2mono(ap[1].x * 0.125f);
        u0.w = f2mono(ap[1].y * 0.125f);
        u1.x = f2mono(ap[2].x * 0.125f);
        u1.y = f2mono(ap[2].y * 0.125f);
        u1.z = f2mono(ap[3].x * 0.125f);
        u1.w = f2mono(ap[3].y * 0.125f);
        *(uint4*)(srow + bcol + tx * 4) = u0;
        *(uint4*)(srow + bcol + 64 + tx * 4) = u1;
    }
}

// ---------------------------------------------------------------------------
// Phase B: per (b,h,s) row — exact top-32 over the stored mono-u32 scores,
// softmax over survivors (exact fp32 via mono2f), V gather, output.
// One warp per row; 8-deep prefetch ring on the score stream.
// ---------------------------------------------------------------------------
__global__ __launch_bounds__(256) void select_kernel(float* __restrict__ out)
{
    const int warp = threadIdx.x >> 5;
    const int lane = threadIdx.x & 31;
    const int job = blockIdx.x * 8 + warp;   // 0..65535
    const int bh = job >> 11;
    const int s  = job & 2047;
    const int b = bh >> 4, h = bh & 15;

    const unsigned* srow = g_S + (size_t)bh * NS * NS + (size_t)s * NS;

    // init list from first 32 candidates
    unsigned lu = srow[lane];
    int lidx = lane;
    unsigned umin = __reduce_min_sync(0xffffffffu, lu);
    int minlane = __ffs(__ballot_sync(0xffffffffu, lu == umin)) - 1;

    // 8-deep prefetch ring
    unsigned nxt[8];
#pragma unroll
    for (int j = 0; j < 8; j++) nxt[j] = srow[(1 + j) * 32 + lane];

#pragma unroll 8
    for (int t = 1; t < 64; t++) {
        const unsigned u = nxt[(t - 1) & 7];
        if (t + 8 < 64) nxt[(t - 1) & 7] = srow[(t + 8) * 32 + lane];
        const int idx = t * 32 + lane;

        unsigned bal = __ballot_sync(0xffffffffu, u > umin);
        while (bal) {
            const int src = __ffs(bal) - 1;
            bal &= bal - 1;
            const unsigned uv = __shfl_sync(0xffffffffu, u, src);
            const int      vi = __shfl_sync(0xffffffffu, idx, src);
            if (uv > umin) {             // umin warp-uniform -> uniform branch
                if (lane == minlane) { lu = uv; lidx = vi; }
                umin = __reduce_min_sync(0xffffffffu, lu);
                minlane = __ffs(__ballot_sync(0xffffffffu, lu == umin)) - 1;
            }
        }
    }

    // softmax over the 32 survivors (== reference masked softmax: masked
    // entries contribute exp(-1e9 - max) == 0 in fp32)
    const float lval = mono2f(lu);
    const float m = warp_max(lval);
    const float e = __expf(lval - m);
    const float w = e / warp_sum(e);

    // AV gather: lane owns output dims (2*lane, 2*lane+1)
    const float* Vb = g_Vp + (size_t)b * NS * ND + h * NDK + lane * 2;
    float2 acc = make_float2(0.f, 0.f);
#pragma unroll
    for (int t = 0; t < 32; t++) {
        const int   vi = __shfl_sync(0xffffffffu, lidx, t);
        const float wt = __shfl_sync(0xffffffffu, w, t);
        const float2 v = *(const float2*)(Vb + (size_t)vi * ND);
        acc.x += wt * v.x;
        acc.y += wt * v.y;
    }

    *(float2*)(out + (size_t)(b * NS + s) * ND + h * NDK + lane * 2) = acc;
}

// ---------------------------------------------------------------------------
extern "C" void kernel_launch(void* const* d_in, const int* in_sizes, int n_in,
                              void* d_out, int out_size)
{
    const float* query = (const float*)d_in[0];
    const float* key   = (const float*)d_in[1];
    const float* value = (const float*)d_in[2];
    const float* Wq    = (const float*)d_in[3];
    const float* bq    = (const float*)d_in[4];
    const float* Wk    = (const float*)d_in[5];
    const float* bk    = (const float*)d_in[6];
    const float* Wv    = (const float*)d_in[7];
    const float* bv    = (const float*)d_in[8];
    float* out = (float*)d_out;

    cudaFuncSetAttribute(score_kernel,
                         cudaFuncAttributeMaxDynamicSharedMemorySize, SCORE_SMEM);

    dim3 pgrid(ND / 128, (NB * NS) / 128, 3);
    proj_kernel<<<pgrid, 256>>>(query, Wq, bq, key, Wk, bk, value, Wv, bv);

    dim3 sgrid(NS / 128, NS / 128, NB * NH);
    score_kernel<<<sgrid, 256, SCORE_SMEM>>>();

    select_kernel<<<(NB * NH * NS) / 8, 256>>>(out);
}

// round 10
// speedup vs baseline: 1.1326x; 1.1326x over previous
#include <cuda_runtime.h>
#include <math.h>

#define NB 2
#define NS 2048
#define ND 1024
#define NH 16
#define NDK 64

// Scratch: projected Q/K/V [B,S,D] fp32 (head h = cols h*64..h*64+63),
// plus full score matrix in order-preserving mono-u32 [BH][S][S] (512 MB).
__device__ float g_Qp[NB * NS * ND];
__device__ float g_Kp[NB * NS * ND];
__device__ float g_Vp[NB * NS * ND];
__device__ unsigned g_S[(size_t)NB * NH * NS * NS];

// ---------------------------------------------------------------------------
// Helpers
// ---------------------------------------------------------------------------
__device__ __forceinline__ float warp_max(float v) {
#pragma unroll
    for (int off = 16; off > 0; off >>= 1)
        v = fmaxf(v, __shfl_xor_sync(0xffffffffu, v, off));
    return v;
}
__device__ __forceinline__ float warp_sum(float v) {
#pragma unroll
    for (int off = 16; off > 0; off >>= 1)
        v += __shfl_xor_sync(0xffffffffu, v, off);
    return v;
}
// Monotone float<->uint transform: u-order == float-order (finite values).
__device__ __forceinline__ unsigned f2mono(float f) {
    unsigned b = __float_as_uint(f);
    return (b & 0x80000000u) ? ~b : (b | 0x80000000u);
}
__device__ __forceinline__ float mono2f(unsigned u) {
    unsigned b = (u & 0x80000000u) ? (u ^ 0x80000000u) : ~u;
    return __uint_as_float(b);
}
// Packed dual-FMA: acc.{lo,hi} += a.{lo,hi} * b.{lo,hi}
__device__ __forceinline__ void ffma2(unsigned long long& acc,
                                      unsigned long long a,
                                      unsigned long long b) {
    asm("fma.rn.f32x2 %0, %1, %2, %0;" : "+l"(acc) : "l"(a), "l"(b));
}
// Duplicate a float into both halves of a packed f32x2
__device__ __forceinline__ unsigned long long dup2(float x) {
    unsigned long long r;
    asm("mov.b64 %0, {%1, %1};" : "=l"(r) : "f"(x));
    return r;
}
union F4U2 { float4 f; unsigned long long u[2]; float s[4]; };

// ---------------------------------------------------------------------------
// Projection GEMM (FFMA2): C = relu(A @ W + bias), M=4096, N=K=1024, x3.
// BK=16, double-buffered smem, one __syncthreads per k-step. (R7 version)
// ---------------------------------------------------------------------------
__global__ __launch_bounds__(256, 2) void proj_kernel(
    const float* __restrict__ X0, const float* __restrict__ W0, const float* __restrict__ B0,
    const float* __restrict__ X1, const float* __restrict__ W1, const float* __restrict__ B1,
    const float* __restrict__ X2, const float* __restrict__ W2, const float* __restrict__ B2)
{
    const int N = ND, K = ND;
    const int z = blockIdx.z;
    const float* A    = (z == 0) ? X0 : (z == 1) ? X1 : X2;
    const float* W    = (z == 0) ? W0 : (z == 1) ? W1 : W2;
    const float* bias = (z == 0) ? B0 : (z == 1) ? B1 : B2;
    float* C          = (z == 0) ? g_Qp : (z == 1) ? g_Kp : g_Vp;

    __shared__ float As[2][16][128];
    __shared__ float Bs[2][16][128];

    const int tid = threadIdx.x;
    const int tx = tid & 15;
    const int ty = tid >> 4;
    const int brow = blockIdx.y * 128;
    const int bcol = blockIdx.x * 128;

    const int ar = tid >> 1;
    const int ak = (tid & 1) << 3;
    const int wr = tid >> 4;
    const int wc = (tid & 15) << 3;

    unsigned long long accp[8][4];
#pragma unroll
    for (int i = 0; i < 8; i++)
#pragma unroll
        for (int q = 0; q < 4; q++) accp[i][q] = 0ull;

    const float* Aptr = A + (size_t)(brow + ar) * K + ak;
    const float* Wptr = W + (size_t)wr * N + bcol + wc;

    float4 a0 = *(const float4*)(Aptr);
    float4 a1 = *(const float4*)(Aptr + 4);
    float4 w0 = *(const float4*)(Wptr);
    float4 w1 = *(const float4*)(Wptr + 4);

    int p = 0;
    for (int k0 = 0; k0 < K; k0 += 16) {
        As[p][ak + 0][ar] = a0.x;
        As[p][ak + 1][ar] = a0.y;
        As[p][ak + 2][ar] = a0.z;
        As[p][ak + 3][ar] = a0.w;
        As[p][ak + 4][ar] = a1.x;
        As[p][ak + 5][ar] = a1.y;
        As[p][ak + 6][ar] = a1.z;
        As[p][ak + 7][ar] = a1.w;
        *(float4*)&Bs[p][wr][wc] = w0;
        *(float4*)&Bs[p][wr][wc + 4] = w1;
        __syncthreads();
        if (k0 + 16 < K) {
            a0 = *(const float4*)(Aptr + k0 + 16);
            a1 = *(const float4*)(Aptr + k0 + 20);
            w0 = *(const float4*)(Wptr + (size_t)(k0 + 16) * N);
            w1 = *(const float4*)(Wptr + (size_t)(k0 + 16) * N + 4);
        }
#pragma unroll
        for (int k = 0; k < 16; k++) {
            float4 av0 = *(const float4*)&As[p][k][ty * 4];
            float4 av1 = *(const float4*)&As[p][k][64 + ty * 4];
            F4U2 b0, b1;
            b0.f = *(const float4*)&Bs[p][k][tx * 4];
            b1.f = *(const float4*)&Bs[p][k][64 + tx * 4];
            unsigned long long bp[4] = {b0.u[0], b0.u[1], b1.u[0], b1.u[1]};
            float arr[8] = {av0.x, av0.y, av0.z, av0.w, av1.x, av1.y, av1.z, av1.w};
#pragma unroll
            for (int i = 0; i < 8; i++) {
                unsigned long long ad = dup2(arr[i]);
#pragma unroll
                for (int q = 0; q < 4; q++) ffma2(accp[i][q], ad, bp[q]);
            }
        }
        p ^= 1;
    }

#pragma unroll
    for (int i = 0; i < 8; i++) {
        const int r = brow + ((i < 4) ? (ty * 4 + i) : (64 + ty * 4 + (i - 4)));
        const float2* ap = (const float2*)&accp[i][0];
        {
            const int c = bcol + tx * 4;
            float4 v;
            v.x = fmaxf(ap[0].x + bias[c + 0], 0.0f);
            v.y = fmaxf(ap[0].y + bias[c + 1], 0.0f);
            v.z = fmaxf(ap[1].x + bias[c + 2], 0.0f);
            v.w = fmaxf(ap[1].y + bias[c + 3], 0.0f);
            *(float4*)(C + (size_t)r * N + c) = v;
        }
        {
            const int c = bcol + 64 + tx * 4;
            float4 v;
            v.x = fmaxf(ap[2].x + bias[c + 0], 0.0f);
            v.y = fmaxf(ap[2].y + bias[c + 1], 0.0f);
            v.z = fmaxf(ap[3].x + bias[c + 2], 0.0f);
            v.w = fmaxf(ap[3].y + bias[c + 3], 0.0f);
            *(float4*)(C + (size_t)r * N + c) = v;
        }
    }
}

// ---------------------------------------------------------------------------
// Phase A: score GEMM (R7 version + bh group offset). Per (b,h):
// S = (Qh @ Kh^T) / 8, written as mono-u32. 128x128 tile / CTA,
// conflict-free split microtile, K=64 in two 32-wide smem phases.
// Grid = (16, 16, GROUP).
// ---------------------------------------------------------------------------
#define SPAD 132
__global__ __launch_bounds__(256, 2) void score_kernel(int bh_base)
{
    __shared__ float As[32][SPAD];   // As[k][m]
    __shared__ float Bs[32][SPAD];   // Bs[k][n]

    const int bh = bh_base + blockIdx.z;
    const int b = bh >> 4, h = bh & 15;
    const int brow = blockIdx.y * 128;
    const int bcol = blockIdx.x * 128;
    const int tid = threadIdx.x;
    const int tx = tid & 15;
    const int ty = tid >> 4;

    const float* Qb = g_Qp + (size_t)b * NS * ND + h * NDK;
    const float* Kb = g_Kp + (size_t)b * NS * ND + h * NDK;

    unsigned long long accp[8][4];
#pragma unroll
    for (int i = 0; i < 8; i++)
#pragma unroll
        for (int q = 0; q < 4; q++) accp[i][q] = 0ull;

    const int d4 = tid & 7;      // float4 index within 32-wide k chunk
    const int rr = tid >> 3;     // 0..31

    for (int kc = 0; kc < 2; kc++) {
        __syncthreads();
#pragma unroll
        for (int c = 0; c < 4; c++) {
            const int r = rr + c * 32;
            float4 qa = *(const float4*)(Qb + (size_t)(brow + r) * ND + kc * 32 + d4 * 4);
            As[d4 * 4 + 0][r] = qa.x;
            As[d4 * 4 + 1][r] = qa.y;
            As[d4 * 4 + 2][r] = qa.z;
            As[d4 * 4 + 3][r] = qa.w;
            float4 kb = *(const float4*)(Kb + (size_t)(bcol + r) * ND + kc * 32 + d4 * 4);
            Bs[d4 * 4 + 0][r] = kb.x;
            Bs[d4 * 4 + 1][r] = kb.y;
            Bs[d4 * 4 + 2][r] = kb.z;
            Bs[d4 * 4 + 3][r] = kb.w;
        }
        __syncthreads();
#pragma unroll 8
        for (int k = 0; k < 32; k++) {
            float4 av0 = *(const float4*)&As[k][ty * 4];
            float4 av1 = *(const float4*)&As[k][64 + ty * 4];
            F4U2 b0, b1;
            b0.f = *(const float4*)&Bs[k][tx * 4];
            b1.f = *(const float4*)&Bs[k][64 + tx * 4];
            unsigned long long bp[4] = {b0.u[0], b0.u[1], b1.u[0], b1.u[1]};
            float arr[8] = {av0.x, av0.y, av0.z, av0.w, av1.x, av1.y, av1.z, av1.w};
#pragma unroll
            for (int i = 0; i < 8; i++) {
                unsigned long long ad = dup2(arr[i]);
#pragma unroll
                for (int q = 0; q < 4; q++) ffma2(accp[i][q], ad, bp[q]);
            }
        }
    }

    // epilogue: scale by 1/8, mono-transform, store u32
    unsigned* Sb = g_S + (size_t)bh * NS * NS;
#pragma unroll
    for (int i = 0; i < 8; i++) {
        const int row = brow + ((i < 4) ? (ty * 4 + i) : (64 + ty * 4 + (i - 4)));
        unsigned* srow = Sb + (size_t)row * NS;
        const float2* ap = (const float2*)&accp[i][0];
        uint4 u0, u1;
        u0.x = f2mono(ap[0].x * 0.125f);
        u0.y = f2mono(ap[0].y * 0.125f);
        u0.z = f2mono(ap[1].x * 0.125f);
        u0.w = f2mono(ap[1].y * 0.125f);
        u1.x = f2mono(ap[2].x * 0.125f);
        u1.y = f2mono(ap[2].y * 0.125f);
        u1.z = f2mono(ap[3].x * 0.125f);
        u1.w = f2mono(ap[3].y * 0.125f);
        *(uint4*)(srow + bcol + tx * 4) = u0;
        *(uint4*)(srow + bcol + 64 + tx * 4) = u1;
    }
}

// ---------------------------------------------------------------------------
// Phase B: per (b,h,s) row — exact top-32 over the stored mono-u32 scores
// (now L2-resident thanks to group interleaving), softmax over survivors,
// V gather, output. One warp per row; 8-deep prefetch ring.
// ---------------------------------------------------------------------------
#define GROUP_BH 4
__global__ __launch_bounds__(256) void select_kernel(float* __restrict__ out,
                                                     int bh_base)
{
    const int warp = threadIdx.x >> 5;
    const int lane = threadIdx.x & 31;
    const int job = blockIdx.x * 8 + warp;    // 0 .. GROUP_BH*2048-1
    const int bh = bh_base + (job >> 11);
    const int s  = job & 2047;
    const int b = bh >> 4, h = bh & 15;

    const unsigned* srow = g_S + (size_t)bh * NS * NS + (size_t)s * NS;

    // init list from first 32 candidates
    unsigned lu = srow[lane];
    int lidx = lane;
    unsigned umin = __reduce_min_sync(0xffffffffu, lu);
    int minlane = __ffs(__ballot_sync(0xffffffffu, lu == umin)) - 1;

    // 8-deep prefetch ring
    unsigned nxt[8];
#pragma unroll
    for (int j = 0; j < 8; j++) nxt[j] = srow[(1 + j) * 32 + lane];

#pragma unroll 8
    for (int t = 1; t < 64; t++) {
        const unsigned u = nxt[(t - 1) & 7];
        if (t + 8 < 64) nxt[(t - 1) & 7] = srow[(t + 8) * 32 + lane];
        const int idx = t * 32 + lane;

        unsigned bal = __ballot_sync(0xffffffffu, u > umin);
        while (bal) {
            const int src = __ffs(bal) - 1;
            bal &= bal - 1;
            const unsigned uv = __shfl_sync(0xffffffffu, u, src);
            const int      vi = __shfl_sync(0xffffffffu, idx, src);
            if (uv > umin) {             // umin warp-uniform -> uniform branch
                if (lane == minlane) { lu = uv; lidx = vi; }
                umin = __reduce_min_sync(0xffffffffu, lu);
                minlane = __ffs(__ballot_sync(0xffffffffu, lu == umin)) - 1;
            }
        }
    }

    // softmax over the 32 survivors (== reference masked softmax: masked
    // entries contribute exp(-1e9 - max) == 0 in fp32)
    const float lval = mono2f(lu);
    const float m = warp_max(lval);
    const float e = __expf(lval - m);
    const float w = e / warp_sum(e);

    // AV gather: lane owns output dims (2*lane, 2*lane+1)
    const float* Vb = g_Vp + (size_t)b * NS * ND + h * NDK + lane * 2;
    float2 acc = make_float2(0.f, 0.f);
#pragma unroll
    for (int t = 0; t < 32; t++) {
        const int   vi = __shfl_sync(0xffffffffu, lidx, t);
        const float wt = __shfl_sync(0xffffffffu, w, t);
        const float2 v = *(const float2*)(Vb + (size_t)vi * ND);
        acc.x += wt * v.x;
        acc.y += wt * v.y;
    }

    *(float2*)(out + (size_t)(b * NS + s) * ND + h * NDK + lane * 2) = acc;
}

// ---------------------------------------------------------------------------
extern "C" void kernel_launch(void* const* d_in, const int* in_sizes, int n_in,
                              void* d_out, int out_size)
{
    const float* query = (const float*)d_in[0];
    const float* key   = (const float*)d_in[1];
    const float* value = (const float*)d_in[2];
    const float* Wq    = (const float*)d_in[3];
    const float* bq    = (const float*)d_in[4];
    const float* Wk    = (const float*)d_in[5];
    const float* bk    = (const float*)d_in[6];
    const float* Wv    = (const float*)d_in[7];
    const float* bv    = (const float*)d_in[8];
    float* out = (float*)d_out;

    dim3 pgrid(ND / 128, (NB * NS) / 128, 3);
    proj_kernel<<<pgrid, 256>>>(query, Wq, bq, key, Wk, bk, value, Wv, bv);

    // Interleave score/select in groups of GROUP_BH (b,h) pairs so each
    // group's 64 MB score slab stays L2-resident for its select pass.
    dim3 sgrid(NS / 128, NS / 128, GROUP_BH);
    const int sel_ctas = (GROUP_BH * NS) / 8;
    for (int g = 0; g < (NB * NH) / GROUP_BH; g++) {
        score_kernel<<<sgrid, 256>>>(g * GROUP_BH);
        select_kernel<<<sel_ctas, 256>>>(out, g * GROUP_BH);
    }
}

// round 13
// speedup vs baseline: 1.2550x; 1.1080x over previous
#include <cuda_runtime.h>
#include <stdint.h>
#include <math.h>

#define NB 2
#define NS 2048
#define ND 1024
#define NH 16
#define NDK 64

// Scratch: projected Q/K/V [B,S,D] fp32 (head h = cols h*64..h*64+63),
// plus full score matrix in order-preserving mono-u32 [BH][S][S] (512 MB).
__device__ float g_Qp[NB * NS * ND];
__device__ float g_Kp[NB * NS * ND];
__device__ float g_Vp[NB * NS * ND];
__device__ unsigned g_S[(size_t)NB * NH * NS * NS];

// ---------------------------------------------------------------------------
// Helpers
// ---------------------------------------------------------------------------
__device__ __forceinline__ float warp_max(float v) {
#pragma unroll
    for (int off = 16; off > 0; off >>= 1)
        v = fmaxf(v, __shfl_xor_sync(0xffffffffu, v, off));
    return v;
}
__device__ __forceinline__ float warp_sum(float v) {
#pragma unroll
    for (int off = 16; off > 0; off >>= 1)
        v += __shfl_xor_sync(0xffffffffu, v, off);
    return v;
}
// Monotone float<->uint transform: u-order == float-order (finite values).
__device__ __forceinline__ unsigned f2mono(float f) {
    unsigned b = __float_as_uint(f);
    return (b & 0x80000000u) ? ~b : (b | 0x80000000u);
}
__device__ __forceinline__ float mono2f(unsigned u) {
    unsigned b = (u & 0x80000000u) ? (u ^ 0x80000000u) : ~u;
    return __uint_as_float(b);
}
// Packed dual-FMA: acc.{lo,hi} += a.{lo,hi} * b.{lo,hi}
__device__ __forceinline__ void ffma2(unsigned long long& acc,
                                      unsigned long long a,
                                      unsigned long long b) {
    asm("fma.rn.f32x2 %0, %1, %2, %0;" : "+l"(acc) : "l"(a), "l"(b));
}
// Duplicate a float into both halves of a packed f32x2
__device__ __forceinline__ unsigned long long dup2(float x) {
    unsigned long long r;
    asm("mov.b64 %0, {%1, %1};" : "=l"(r) : "f"(x));
    return r;
}
union F4U2 { float4 f; unsigned long long u[2]; float s[4]; };

// ---------------------------------------------------------------------------
// Projection GEMM (FFMA2): C = relu(A @ W + bias), M=4096, N=K=1024, x3.
// (R7 version, local optimum — verbatim)
// ---------------------------------------------------------------------------
__global__ __launch_bounds__(256, 2) void proj_kernel(
    const float* __restrict__ X0, const float* __restrict__ W0, const float* __restrict__ B0,
    const float* __restrict__ X1, const float* __restrict__ W1, const float* __restrict__ B1,
    const float* __restrict__ X2, const float* __restrict__ W2, const float* __restrict__ B2)
{
    const int N = ND, K = ND;
    const int z = blockIdx.z;
    const float* A    = (z == 0) ? X0 : (z == 1) ? X1 : X2;
    const float* W    = (z == 0) ? W0 : (z == 1) ? W1 : W2;
    const float* bias = (z == 0) ? B0 : (z == 1) ? B1 : B2;
    float* C          = (z == 0) ? g_Qp : (z == 1) ? g_Kp : g_Vp;

    __shared__ float As[2][16][128];
    __shared__ float Bs[2][16][128];

    const int tid = threadIdx.x;
    const int tx = tid & 15;
    const int ty = tid >> 4;
    const int brow = blockIdx.y * 128;
    const int bcol = blockIdx.x * 128;

    const int ar = tid >> 1;
    const int ak = (tid & 1) << 3;
    const int wr = tid >> 4;
    const int wc = (tid & 15) << 3;

    unsigned long long accp[8][4];
#pragma unroll
    for (int i = 0; i < 8; i++)
#pragma unroll
        for (int q = 0; q < 4; q++) accp[i][q] = 0ull;

    const float* Aptr = A + (size_t)(brow + ar) * K + ak;
    const float* Wptr = W + (size_t)wr * N + bcol + wc;

    float4 a0 = *(const float4*)(Aptr);
    float4 a1 = *(const float4*)(Aptr + 4);
    float4 w0 = *(const float4*)(Wptr);
    float4 w1 = *(const float4*)(Wptr + 4);

    int p = 0;
    for (int k0 = 0; k0 < K; k0 += 16) {
        As[p][ak + 0][ar] = a0.x;
        As[p][ak + 1][ar] = a0.y;
        As[p][ak + 2][ar] = a0.z;
        As[p][ak + 3][ar] = a0.w;
        As[p][ak + 4][ar] = a1.x;
        As[p][ak + 5][ar] = a1.y;
        As[p][ak + 6][ar] = a1.z;
        As[p][ak + 7][ar] = a1.w;
        *(float4*)&Bs[p][wr][wc] = w0;
        *(float4*)&Bs[p][wr][wc + 4] = w1;
        __syncthreads();
        if (k0 + 16 < K) {
            a0 = *(const float4*)(Aptr + k0 + 16);
            a1 = *(const float4*)(Aptr + k0 + 20);
            w0 = *(const float4*)(Wptr + (size_t)(k0 + 16) * N);
            w1 = *(const float4*)(Wptr + (size_t)(k0 + 16) * N + 4);
        }
#pragma unroll
        for (int k = 0; k < 16; k++) {
            float4 av0 = *(const float4*)&As[p][k][ty * 4];
            float4 av1 = *(const float4*)&As[p][k][64 + ty * 4];
            F4U2 b0, b1;
            b0.f = *(const float4*)&Bs[p][k][tx * 4];
            b1.f = *(const float4*)&Bs[p][k][64 + tx * 4];
            unsigned long long bp[4] = {b0.u[0], b0.u[1], b1.u[0], b1.u[1]};
            float arr[8] = {av0.x, av0.y, av0.z, av0.w, av1.x, av1.y, av1.z, av1.w};
#pragma unroll
            for (int i = 0; i < 8; i++) {
                unsigned long long ad = dup2(arr[i]);
#pragma unroll
                for (int q = 0; q < 4; q++) ffma2(accp[i][q], ad, bp[q]);
            }
        }
        p ^= 1;
    }

#pragma unroll
    for (int i = 0; i < 8; i++) {
        const int r = brow + ((i < 4) ? (ty * 4 + i) : (64 + ty * 4 + (i - 4)));
        const float2* ap = (const float2*)&accp[i][0];
        {
            const int c = bcol + tx * 4;
            float4 v;
            v.x = fmaxf(ap[0].x + bias[c + 0], 0.0f);
            v.y = fmaxf(ap[0].y + bias[c + 1], 0.0f);
            v.z = fmaxf(ap[1].x + bias[c + 2], 0.0f);
            v.w = fmaxf(ap[1].y + bias[c + 3], 0.0f);
            *(float4*)(C + (size_t)r * N + c) = v;
        }
        {
            const int c = bcol + 64 + tx * 4;
            float4 v;
            v.x = fmaxf(ap[2].x + bias[c + 0], 0.0f);
            v.y = fmaxf(ap[2].y + bias[c + 1], 0.0f);
            v.z = fmaxf(ap[3].x + bias[c + 2], 0.0f);
            v.w = fmaxf(ap[3].y + bias[c + 3], 0.0f);
            *(float4*)(C + (size_t)r * N + c) = v;
        }
    }
}

// ---------------------------------------------------------------------------
// Phase A: score GEMM (R7 version, verbatim). Per (b,h):
// S = (Qh @ Kh^T) / 8, written as mono-u32. 128x128 tile / CTA,
// conflict-free split microtile, K=64 in two 32-wide smem phases.
// Grid = (16, 16, 32).
// ---------------------------------------------------------------------------
#define SPAD 132
__global__ __launch_bounds__(256, 2) void score_kernel()
{
    __shared__ float As[32][SPAD];   // As[k][m]
    __shared__ float Bs[32][SPAD];   // Bs[k][n]

    const int bh = blockIdx.z;
    const int b = bh >> 4, h = bh & 15;
    const int brow = blockIdx.y * 128;
    const int bcol = blockIdx.x * 128;
    const int tid = threadIdx.x;
    const int tx = tid & 15;
    const int ty = tid >> 4;

    const float* Qb = g_Qp + (size_t)b * NS * ND + h * NDK;
    const float* Kb = g_Kp + (size_t)b * NS * ND + h * NDK;

    unsigned long long accp[8][4];
#pragma unroll
    for (int i = 0; i < 8; i++)
#pragma unroll
        for (int q = 0; q < 4; q++) accp[i][q] = 0ull;

    const int d4 = tid & 7;      // float4 index within 32-wide k chunk
    const int rr = tid >> 3;     // 0..31

    for (int kc = 0; kc < 2; kc++) {
        __syncthreads();
#pragma unroll
        for (int c = 0; c < 4; c++) {
            const int r = rr + c * 32;
            float4 qa = *(const float4*)(Qb + (size_t)(brow + r) * ND + kc * 32 + d4 * 4);
            As[d4 * 4 + 0][r] = qa.x;
            As[d4 * 4 + 1][r] = qa.y;
            As[d4 * 4 + 2][r] = qa.z;
            As[d4 * 4 + 3][r] = qa.w;
            float4 kb = *(const float4*)(Kb + (size_t)(bcol + r) * ND + kc * 32 + d4 * 4);
            Bs[d4 * 4 + 0][r] = kb.x;
            Bs[d4 * 4 + 1][r] = kb.y;
            Bs[d4 * 4 + 2][r] = kb.z;
            Bs[d4 * 4 + 3][r] = kb.w;
        }
        __syncthreads();
#pragma unroll 8
        for (int k = 0; k < 32; k++) {
            float4 av0 = *(const float4*)&As[k][ty * 4];
            float4 av1 = *(const float4*)&As[k][64 + ty * 4];
            F4U2 b0, b1;
            b0.f = *(const float4*)&Bs[k][tx * 4];
            b1.f = *(const float4*)&Bs[k][64 + tx * 4];
            unsigned long long bp[4] = {b0.u[0], b0.u[1], b1.u[0], b1.u[1]};
            float arr[8] = {av0.x, av0.y, av0.z, av0.w, av1.x, av1.y, av1.z, av1.w};
#pragma unroll
            for (int i = 0; i < 8; i++) {
                unsigned long long ad = dup2(arr[i]);
#pragma unroll
                for (int q = 0; q < 4; q++) ffma2(accp[i][q], ad, bp[q]);
            }
        }
    }

    // epilogue: scale by 1/8, mono-transform, store u32
    unsigned* Sb = g_S + (size_t)bh * NS * NS;
#pragma unroll
    for (int i = 0; i < 8; i++) {
        const int row = brow + ((i < 4) ? (ty * 4 + i) : (64 + ty * 4 + (i - 4)));
        unsigned* srow = Sb + (size_t)row * NS;
        const float2* ap = (const float2*)&accp[i][0];
        uint4 u0, u1;
        u0.x = f2mono(ap[0].x * 0.125f);
        u0.y = f2mono(ap[0].y * 0.125f);
        u0.z = f2mono(ap[1].x * 0.125f);
        u0.w = f2mono(ap[1].y * 0.125f);
        u1.x = f2mono(ap[2].x * 0.125f);
        u1.y = f2mono(ap[2].y * 0.125f);
        u1.z = f2mono(ap[3].x * 0.125f);
        u1.w = f2mono(ap[3].y * 0.125f);
        *(uint4*)(srow + bcol + tx * 4) = u0;
        *(uint4*)(srow + bcol + 64 + tx * 4) = u1;
    }
}

// ---------------------------------------------------------------------------
// Phase B: per (b,h,s) row — exact top-32 over the stored mono-u32 scores,
// softmax over survivors, V gather, output. One warp per row; 8-deep
// prefetch ring. Shuffle diet vs R7 (selection decisions bit-identical):
//   - accepted candidate's index = t*32 + src (no shfl needed)
//   - AV gather weights/indices broadcast through smem (LDS) not shfl
// ---------------------------------------------------------------------------
__global__ __launch_bounds__(256) void select_kernel(float* __restrict__ out)
{
    __shared__ float swt[8][32];
    __shared__ int   svi[8][32];

    const int warp = threadIdx.x >> 5;
    const int lane = threadIdx.x & 31;
    const int job = blockIdx.x * 8 + warp;   // 0..65535
    const int bh = job >> 11;
    const int s  = job & 2047;
    const int b = bh >> 4, h = bh & 15;

    const unsigned* srow = g_S + (size_t)bh * NS * NS + (size_t)s * NS;

    // init list from first 32 candidates
    unsigned lu = srow[lane];
    int lidx = lane;
    unsigned umin = __reduce_min_sync(0xffffffffu, lu);
    int minlane = __ffs(__ballot_sync(0xffffffffu, lu == umin)) - 1;

    // 8-deep prefetch ring
    unsigned nxt[8];
#pragma unroll
    for (int j = 0; j < 8; j++) nxt[j] = srow[(1 + j) * 32 + lane];

#pragma unroll 8
    for (int t = 1; t < 64; t++) {
        const unsigned u = nxt[(t - 1) & 7];
        if (t + 8 < 64) nxt[(t - 1) & 7] = srow[(t + 8) * 32 + lane];
        const int base = t * 32;

        unsigned bal = __ballot_sync(0xffffffffu, u > umin);
        while (bal) {
            const int src = __ffs(bal) - 1;
            bal &= bal - 1;
            const unsigned uv = __shfl_sync(0xffffffffu, u, src);
            if (uv > umin) {             // umin warp-uniform -> uniform branch
                if (lane == minlane) { lu = uv; lidx = base + src; }
                umin = __reduce_min_sync(0xffffffffu, lu);
                minlane = __ffs(__ballot_sync(0xffffffffu, lu == umin)) - 1;
            }
        }
    }

    // softmax over the 32 survivors (== reference masked softmax: masked
    // entries contribute exp(-1e9 - max) == 0 in fp32)
    const float lval = mono2f(lu);
    const float m = warp_max(lval);
    const float e = __expf(lval - m);
    const float w = e / warp_sum(e);

    // publish (weight, index) via smem; gather loop uses LDS broadcasts
    swt[warp][lane] = w;
    svi[warp][lane] = lidx;
    __syncwarp();

    // AV gather: lane owns output dims (2*lane, 2*lane+1)
    const float* Vb = g_Vp + (size_t)b * NS * ND + h * NDK + lane * 2;
    float2 acc = make_float2(0.f, 0.f);
#pragma unroll
    for (int t = 0; t < 32; t++) {
        const int   vi = svi[warp][t];
        const float wt = swt[warp][t];
        const float2 v = *(const float2*)(Vb + (size_t)vi * ND);
        acc.x += wt * v.x;
        acc.y += wt * v.y;
    }

    *(float2*)(out + (size_t)(b * NS + s) * ND + h * NDK + lane * 2) = acc;
}

// ---------------------------------------------------------------------------
extern "C" void kernel_launch(void* const* d_in, const int* in_sizes, int n_in,
                              void* d_out, int out_size)
{
    const float* query = (const float*)d_in[0];
    const float* key   = (const float*)d_in[1];
    const float* value = (const float*)d_in[2];
    const float* Wq    = (const float*)d_in[3];
    const float* bq    = (const float*)d_in[4];
    const float* Wk    = (const float*)d_in[5];
    const float* bk    = (const float*)d_in[6];
    const float* Wv    = (const float*)d_in[7];
    const float* bv    = (const float*)d_in[8];
    float* out = (float*)d_out;

    dim3 pgrid(ND / 128, (NB * NS) / 128, 3);
    proj_kernel<<<pgrid, 256>>>(query, Wq, bq, key, Wk, bk, value, Wv, bv);

    dim3 sgrid(NS / 128, NS / 128, NB * NH);
    score_kernel<<<sgrid, 256>>>();

    select_kernel<<<(NB * NH * NS) / 8, 256>>>(out);
}